// round 6
// baseline (speedup 1.0000x reference)
#include <cuda_runtime.h>
#include <stdint.h>
#include <math.h>

// ---------------------------------------------------------------------------
// InteractionPredictor e3nn-GNN forward, fp32. GEMM + L2-chunked pipeline +
// packed f32x2 FMA.
// ---------------------------------------------------------------------------
#define NMAX  16384
#define CH    20480                       // chunk size (edges) for L2 residency

__device__ float g_nodeA[NMAX * 40];
__device__ float g_nodeB[NMAX * 40];
__device__ float g_msgs [NMAX * 40];
__device__ __align__(16) float g_tw[320 * 512];          // transposed rec_w1
__device__ __align__(16) float g_Wg[(size_t)CH * 576];   // chunk TP weights
__device__ __align__(16) float g_Hl[CH * 64];
__device__ __align__(16) float g_Hr[CH * 64];
__device__ __align__(16) float g_Zt[(size_t)320 * CH];   // transposed Z chunk
__device__ __align__(16) float g_M [(size_t)CH * 512];
__device__ float g_rh[CH * 3];

#define ACT_NORM 1.6789717f
#define PW0_8    0.025515518153991443f   // sqrt(1/24)/8  (== pw1/sqrt3/8)
#define PW1_8    0.044194173824159216f   // sqrt(1/8)/8
#define PWREC_8  0.006987712429686843f   // sqrt(1/320)/8
#define INV_SQ3  0.57735026918962576f
#define DEMB_C   37.716086f              // 1.14136 * e^2 * sqrt(20)

__device__ __forceinline__ float silu_act(float s) {
    return s / (1.f + expf(-s)) * ACT_NORM;
}

// ---- packed fp32x2 helpers -------------------------------------------------
__device__ __forceinline__ unsigned long long ffma2(
        unsigned long long a, unsigned long long b, unsigned long long c) {
    unsigned long long d;
    asm("fma.rn.f32x2 %0, %1, %2, %3;" : "=l"(d) : "l"(a), "l"(b), "l"(c));
    return d;
}
__device__ __forceinline__ unsigned long long fpack2(float lo, float hi) {
    unsigned long long d;
    asm("mov.b64 %0, {%1, %2};" : "=l"(d) : "f"(lo), "f"(hi));
    return d;
}
__device__ __forceinline__ float2 funpack2(unsigned long long d) {
    float lo, hi;
    asm("mov.b64 {%0, %1}, %2;" : "=f"(lo), "=f"(hi) : "l"(d));
    return make_float2(lo, hi);
}

__device__ __forceinline__ void cpa16(unsigned int dst, const void* src) {
    asm volatile("cp.async.ca.shared.global [%0], [%1], 16;" :: "r"(dst), "l"(src));
}
__device__ __forceinline__ void cpa_commit() {
    asm volatile("cp.async.commit_group;");
}
__device__ __forceinline__ void cpa_wait0() {
    asm volatile("cp.async.wait_group 0;");
}

// Shared GEMM microkernel body: 128x64 tile, acc packed along M.
// As: [k][LDA] (m fast), Bs: [k][64]. Requires (LDA*4)%16==0.
template<int KLEN, int LDA>
__device__ __forceinline__ void gemm_core(
        const float* As, const float* Bs, unsigned long long acc[4][4],
        int tx, int ty) {
    #pragma unroll 8
    for (int k = 0; k < KLEN; k++) {
        float4 b4 = *(const float4*)&Bs[k * 64 + tx * 4];
        unsigned long long bx = fpack2(b4.x, b4.x);
        unsigned long long by = fpack2(b4.y, b4.y);
        unsigned long long bz = fpack2(b4.z, b4.z);
        unsigned long long bw = fpack2(b4.w, b4.w);
        const ulonglong2* ap = (const ulonglong2*)&As[k * LDA + ty * 8];
        ulonglong2 A0 = ap[0];
        ulonglong2 A1 = ap[1];
        unsigned long long av[4] = {A0.x, A0.y, A1.x, A1.y};
        #pragma unroll
        for (int mi = 0; mi < 4; mi++) {
            acc[mi][0] = ffma2(av[mi], bx, acc[mi][0]);
            acc[mi][1] = ffma2(av[mi], by, acc[mi][1]);
            acc[mi][2] = ffma2(av[mi], bz, acc[mi][2]);
            acc[mi][3] = ffma2(av[mi], bw, acc[mi][3]);
        }
    }
}

__device__ __forceinline__ void gemm_store(
        unsigned long long acc[4][4], float* C, int ldc,
        int rowBase, int nBase, int M, int tx, int ty) {
    #pragma unroll
    for (int mi = 0; mi < 4; mi++) {
        float2 c0 = funpack2(acc[mi][0]);
        float2 c1 = funpack2(acc[mi][1]);
        float2 c2 = funpack2(acc[mi][2]);
        float2 c3 = funpack2(acc[mi][3]);
        int r0 = rowBase + ty * 8 + mi * 2;
        if (r0 < M)
            *(float4*)(C + (size_t)r0 * ldc + nBase + tx * 4) =
                make_float4(c0.x, c1.x, c2.x, c3.x);
        if (r0 + 1 < M)
            *(float4*)(C + (size_t)(r0 + 1) * ldc + nBase + tx * 4) =
                make_float4(c0.y, c1.y, c2.y, c3.y);
    }
}

// ---------------------------------------------------------------------------
// Transpose rec_w1 [64,2560] -> TW[320,512]
// ---------------------------------------------------------------------------
__global__ void k_transpose(const float* __restrict__ rw1) {
    int idx = blockIdx.x * 256 + threadIdx.x;
    if (idx >= 320 * 512) return;
    int p = idx >> 9, r = idx & 511;
    int k = r >> 3, w = r & 7;
    g_tw[idx] = rw1[k * 2560 + p * 8 + w];
}

// ---------------------------------------------------------------------------
// Node embedding MLP + zero geo + zero msgs. One warp per node.
// ---------------------------------------------------------------------------
__global__ void k_embed(const float* __restrict__ x,
                        const float* __restrict__ w0,   // [10,64]
                        const float* __restrict__ w1,   // [64,16]
                        int N) {
    __shared__ float sh[8][64];
    int warp = threadIdx.x >> 5, lane = threadIdx.x & 31;
    int n = blockIdx.x * 8 + warp;
    if (n >= N) return;
    float xa[10];
    #pragma unroll
    for (int a = 0; a < 10; a++) xa[a] = x[n * 10 + a];
    #pragma unroll
    for (int r = 0; r < 2; r++) {
        int k = lane + r * 32;
        float s = 0.f;
        #pragma unroll
        for (int a = 0; a < 10; a++) s += xa[a] * w0[a * 64 + k];
        sh[warp][k] = silu_act(s * 0.31622776601683794f);   // 1/sqrt(10)
    }
    __syncwarp();
    if (lane < 16) {
        float s = 0.f;
        #pragma unroll
        for (int k = 0; k < 64; k++) s += sh[warp][k] * w1[k * 16 + lane];
        g_nodeA[n * 40 + lane] = s * 0.125f;                // 1/sqrt(64)
    }
    if (lane < 24) g_nodeA[n * 40 + 16 + lane] = 0.f;
    g_msgs[n * 40 + lane] = 0.f;
    if (lane < 8) g_msgs[n * 40 + 32 + lane] = 0.f;
}

// ---------------------------------------------------------------------------
// Fused msg weight GEMM: W[ec,576] = silu(eattr @ mw0 /sqrt5) @ mw1.
// ---------------------------------------------------------------------------
__global__ void __launch_bounds__(256) k_wgemm_msg(
        const float* __restrict__ eattr,
        const float* __restrict__ mw0,   // [5,64]
        const float* __restrict__ mw1,   // [64,576]
        float* __restrict__ C, int E) {
    extern __shared__ float sm[];
    float* As  = sm;               // [64][128]
    float* Bs  = As + 8192;        // [64][64]
    float* Ea  = Bs + 4096;        // [128*5]
    float* W0s = Ea + 640;         // [5*64]
    int t = threadIdx.x;
    int rowBase = blockIdx.y * 128;
    int nBase   = blockIdx.x * 64;

    for (int idx = t; idx < 640; idx += 256) {
        int r = idx / 5;
        Ea[idx] = (rowBase + r < E) ? eattr[(size_t)rowBase * 5 + idx] : 0.f;
    }
    if (t < 64) W0s[256 + t] = mw0[256 + t];
    W0s[t] = mw0[t];
    #pragma unroll
    for (int i = 0; i < 16; i++) {
        int idx = t + i * 256;
        int k = idx >> 6, n = idx & 63;
        Bs[idx] = mw1[k * 576 + nBase + n];
    }
    __syncthreads();

    {   // hidden: thread (r=t>>1) computes k=(t&1)*32..+31
        int r = t >> 1, kb = (t & 1) * 32;
        float ea[5];
        #pragma unroll
        for (int a = 0; a < 5; a++) ea[a] = Ea[r * 5 + a];
        #pragma unroll
        for (int kk = 0; kk < 32; kk++) {
            int k = kb + kk;
            float s = 0.f;
            #pragma unroll
            for (int a = 0; a < 5; a++) s += ea[a] * W0s[a * 64 + k];
            As[k * 128 + r] = silu_act(s * 0.4472135954999579f);   // 1/sqrt(5)
        }
    }
    __syncthreads();

    int tx = t & 15, ty = t >> 4;
    unsigned long long acc[4][4] = {};
    gemm_core<64, 128>(As, Bs, acc, tx, ty);
    gemm_store(acc, C, 576, rowBase, nBase, E, tx, ty);
}

// ---------------------------------------------------------------------------
// K=64 GEMM, A from global row-major: C[M,576] = A[M,64] @ B[64,576].
// ---------------------------------------------------------------------------
__global__ void __launch_bounds__(256) k_gemm64(
        const float* __restrict__ A, const float* __restrict__ B,
        float* __restrict__ C, int M) {
    extern __shared__ float sm[];
    float* As = sm;                // [64][132] padded
    float* Bs = As + 64 * 132;     // [64][64]
    int t = threadIdx.x;
    int rowBase = blockIdx.y * 128;
    int nBase   = blockIdx.x * 64;
    int ar = t >> 3, ac4 = (t & 7) * 4;
    #pragma unroll
    for (int i = 0; i < 4; i++) {
        int r = rowBase + ar + 32 * i;
        #pragma unroll
        for (int h = 0; h < 2; h++) {
            int kc = ac4 + h * 32;
            float4 v = make_float4(0.f, 0.f, 0.f, 0.f);
            if (r < M) v = *(const float4*)(A + (size_t)r * 64 + kc);
            As[(kc + 0) * 132 + ar + 32 * i] = v.x;
            As[(kc + 1) * 132 + ar + 32 * i] = v.y;
            As[(kc + 2) * 132 + ar + 32 * i] = v.z;
            As[(kc + 3) * 132 + ar + 32 * i] = v.w;
        }
    }
    #pragma unroll
    for (int i = 0; i < 16; i++) {
        int idx = t + i * 256;
        int k = idx >> 6, n = idx & 63;
        Bs[idx] = B[k * 576 + nBase + n];
    }
    __syncthreads();
    int tx = t & 15, ty = t >> 4;
    unsigned long long acc[4][4] = {};
    gemm_core<64, 132>(As, Bs, acc, tx, ty);
    gemm_store(acc, C, 576, rowBase, nBase, M, tx, ty);
}

// ---------------------------------------------------------------------------
// Rec GEMM: M[ec,512] = Z @ TW. A = Zt (K-major [320][CH]), B = TW [320,512].
// BK=32, cp.async double-buffered.
// ---------------------------------------------------------------------------
__global__ void __launch_bounds__(256) k_gemm_rec(
        const float* __restrict__ Zt, const float* __restrict__ TW,
        float* __restrict__ C, int M) {
    extern __shared__ float sm[];
    float* As = sm;            // [2][32][128]
    float* Bs = As + 8192;     // [2][32][64]
    unsigned int sAs = (unsigned int)__cvta_generic_to_shared(As);
    unsigned int sBs = (unsigned int)__cvta_generic_to_shared(Bs);
    int t = threadIdx.x;
    int rowBase = blockIdx.y * 128;
    int nBase   = blockIdx.x * 64;
    int tx = t & 15, ty = t >> 4;

    {
        #pragma unroll
        for (int i = 0; i < 4; i++) {
            int c = t + i * 256;
            int kr = c >> 5, c4 = (c & 31) * 4;
            cpa16(sAs + (kr * 128 + c4) * 4, Zt + (size_t)kr * CH + rowBase + c4);
        }
        #pragma unroll
        for (int i = 0; i < 2; i++) {
            int c = t + i * 256;
            int kr = c >> 4, c4 = (c & 15) * 4;
            cpa16(sBs + (kr * 64 + c4) * 4, TW + kr * 512 + nBase + c4);
        }
        cpa_commit();
    }

    unsigned long long acc[4][4] = {};
    for (int it = 0; it < 10; it++) {
        cpa_wait0();
        __syncthreads();
        if (it + 1 < 10) {
            int k0 = (it + 1) * 32;
            int b = (it + 1) & 1;
            #pragma unroll
            for (int i = 0; i < 4; i++) {
                int c = t + i * 256;
                int kr = c >> 5, c4 = (c & 31) * 4;
                cpa16(sAs + (b * 4096 + kr * 128 + c4) * 4,
                      Zt + (size_t)(k0 + kr) * CH + rowBase + c4);
            }
            #pragma unroll
            for (int i = 0; i < 2; i++) {
                int c = t + i * 256;
                int kr = c >> 4, c4 = (c & 15) * 4;
                cpa16(sBs + (b * 2048 + kr * 64 + c4) * 4,
                      TW + (k0 + kr) * 512 + nBase + c4);
            }
            cpa_commit();
        }
        gemm_core<32, 128>(As + (it & 1) * 4096, Bs + (it & 1) * 2048, acc, tx, ty);
        __syncthreads();
    }
    gemm_store(acc, C, 512, rowBase, nBase, M, tx, ty);
}

// ---------------------------------------------------------------------------
// TP + scatter: 32 edges/block, W read from (L2-hot) chunk buffer.
// ---------------------------------------------------------------------------
__global__ void __launch_bounds__(256) k_tp_scatter(
        const float* __restrict__ pos,
        const int* __restrict__ src, const int* __restrict__ dst,
        const float* __restrict__ Wg, int E, int use_b) {
    extern __shared__ float sm[];
    float* sh_w   = sm;                  // 32*577 = 18464
    float* sh_f   = sh_w + 18464;        // 1280
    float* sh_dot = sh_f + 1280;         // 256
    float* sh_r   = sh_dot + 256;        // 96
    int*   sh_src = (int*)(sh_r + 96);
    int*   sh_dst = sh_src + 32;
    const float* node = use_b ? g_nodeB : g_nodeA;
    int t = threadIdx.x;
    int ebase = blockIdx.x * 32;
    int nval = min(32, E - ebase);

    if (t < 32) {
        sh_src[t] = (t < nval) ? src[ebase + t] : 0;
        sh_dst[t] = (t < nval) ? dst[ebase + t] : -1;
    }
    __syncthreads();
    for (int idx = t; idx < nval * 576; idx += 256) {
        int e = idx / 576, j = idx - e * 576;
        sh_w[e * 577 + j] = Wg[(size_t)ebase * 576 + idx];
    }
    for (int idx = t; idx < 1280; idx += 256) {
        int e = idx / 40, f = idx - e * 40;
        sh_f[idx] = (sh_dst[e] >= 0) ? node[sh_src[e] * 40 + f] : 0.f;
    }
    if (t < 32) {
        float rx = 0.f, ry = 0.f, rz = 0.f;
        if (sh_dst[t] >= 0) {
            const float* ps = pos + sh_src[t] * 3;
            const float* pd = pos + sh_dst[t] * 3;
            rx = pd[0] - ps[0]; ry = pd[1] - ps[1]; rz = pd[2] - ps[2];
            float inv = rsqrtf(rx * rx + ry * ry + rz * rz);
            rx *= inv; ry *= inv; rz *= inv;
        }
        sh_r[t * 3] = rx; sh_r[t * 3 + 1] = ry; sh_r[t * 3 + 2] = rz;
    }
    __syncthreads();
    {
        int e = t >> 3, u = t & 7;
        sh_dot[t] = sh_f[e * 40 + 16 + u * 3] * sh_r[e * 3]
                  + sh_f[e * 40 + 17 + u * 3] * sh_r[e * 3 + 1]
                  + sh_f[e * 40 + 18 + u * 3] * sh_r[e * 3 + 2];
    }
    __syncthreads();
    for (int idx = t; idx < 1280; idx += 256) {
        int e = idx / 40, o = idx - e * 40;
        int d = sh_dst[e];
        if (d < 0) continue;
        const float* w = sh_w + e * 577;
        const float* f = sh_f + e * 40;
        float val;
        if (o < 16) {
            float s1 = 0.f, s2 = 0.f;
            #pragma unroll
            for (int u = 0; u < 16; u++) s1 += f[u] * w[u * 16 + o];
            #pragma unroll
            for (int u = 0; u < 8; u++)  s2 += sh_dot[e * 8 + u] * w[256 + u * 16 + o];
            val = PW0_8 * (s1 + s2);
        } else {
            int v = o - 16; int wv = v / 3; int i = v - wv * 3;
            float s1 = 0.f, s2 = 0.f;
            #pragma unroll
            for (int u = 0; u < 16; u++) s1 += f[u] * w[384 + u * 8 + wv];
            #pragma unroll
            for (int u = 0; u < 8; u++)  s2 += f[16 + u * 3 + i] * w[512 + u * 8 + wv];
            val = PW1_8 * s1 * sh_r[e * 3 + i] + PW0_8 * s2;
        }
        atomicAdd(&g_msgs[d * 40 + o], val);
    }
}

// ---------------------------------------------------------------------------
// Update step. Re-zeroes g_msgs.
// ---------------------------------------------------------------------------
__global__ void k_upd(const float* __restrict__ uw0,   // [32,64]
                      const float* __restrict__ uw1,   // [64,16]
                      const float* __restrict__ imp,
                      int N, float degInv, int step) {
    __shared__ float cat[8][32];
    __shared__ float hh[8][64];
    int warp = threadIdx.x >> 5, lane = threadIdx.x & 31;
    int n = blockIdx.x * 8 + warp;
    if (n >= N) return;
    const float* in = step ? g_nodeB : g_nodeA;
    float* out = step ? g_nodeA : g_nodeB;
    float sc = imp[0] * degInv;
    float gscale = step ? 0.5f : 1.0f;
    if (lane < 16) {
        cat[warp][lane]      = g_msgs[n * 40 + lane] * sc;
        cat[warp][16 + lane] = in[n * 40 + lane];
    }
    __syncwarp();
    #pragma unroll
    for (int r = 0; r < 2; r++) {
        int k = lane + r * 32;
        float s = 0.f;
        #pragma unroll
        for (int a = 0; a < 32; a++) s += cat[warp][a] * uw0[a * 64 + k];
        hh[warp][k] = silu_act(s * 0.17677669529663687f);   // 1/sqrt(32)
    }
    __syncwarp();
    if (lane < 16) {
        float s = 0.f;
        #pragma unroll
        for (int k = 0; k < 64; k++) s += hh[warp][k] * uw1[k * 16 + lane];
        out[n * 40 + lane] = s * 0.125f;
    }
    if (lane < 24)
        out[n * 40 + 16 + lane] =
            (g_msgs[n * 40 + 16 + lane] * sc + in[n * 40 + 16 + lane]) * gscale;
    g_msgs[n * 40 + lane] = 0.f;
    if (lane < 8) g_msgs[n * 40 + 32 + lane] = 0.f;
}

// ---------------------------------------------------------------------------
// Inter-edge prep (chunk-local): rhat + dist-embed -> Hl, Hr.
// ---------------------------------------------------------------------------
__global__ void k_prep(const float* __restrict__ pos,
                       const int* __restrict__ irec, const int* __restrict__ ilig,
                       const float* __restrict__ lw0,   // [20,64]
                       const float* __restrict__ rw0,   // [20,64]
                       int EC) {
    int idx = blockIdx.x * 256 + threadIdx.x;
    int e = idx >> 6, k = idx & 63;
    if (e >= EC) return;
    int ir = irec[e], il = ilig[e];
    float rx = pos[il * 3]     - pos[ir * 3];
    float ry = pos[il * 3 + 1] - pos[ir * 3 + 1];
    float rz = pos[il * 3 + 2] - pos[ir * 3 + 2];
    float d = sqrtf(rx * rx + ry * ry + rz * rz);
    float inv = 1.f / d;
    if (k == 0) {
        g_rh[e * 3]     = rx * inv;
        g_rh[e * 3 + 1] = ry * inv;
        g_rh[e * 3 + 2] = rz * inv;
    }
    float s1 = 0.f, s2 = 0.f;
    #pragma unroll
    for (int a = 0; a < 20; a++) {
        float diff = d * (21.f / 5.f) - (float)(a + 1);
        float t1 = diff + 1.f, t2 = 1.f - diff;
        float v = 0.f;
        if (t1 > 0.f && t2 > 0.f) v = DEMB_C * expf(-1.f / t1 - 1.f / t2);
        s1 += v * lw0[a * 64 + k];
        s2 += v * rw0[a * 64 + k];
    }
    g_Hl[idx] = silu_act(s1 * 0.22360679774997896f);   // 1/sqrt(20)
    g_Hr[idx] = silu_act(s2 * 0.22360679774997896f);
}

// ---------------------------------------------------------------------------
// lig TP + Z outer-product (chunk-local, writes transposed Zt).
// ---------------------------------------------------------------------------
__global__ void __launch_bounds__(256) k_lig_tp_z(
        const int* __restrict__ irec, const int* __restrict__ ilig,
        const float* __restrict__ Wl, int EC) {
    extern __shared__ float sm[];
    float* sh_w   = sm;                 // 16*577 = 9232
    float* sh_fl  = sh_w + 9232;        // 640
    float* sh_fr  = sh_fl + 640;        // 640
    float* sh_dot = sh_fr + 640;        // 128
    float* sh_r   = sh_dot + 128;       // 48
    float* sh_le  = sh_r + 48;          // 640
    int* sh_il = (int*)(sh_le + 640);
    int* sh_ir = sh_il + 16;
    int t = threadIdx.x;
    int ebase = blockIdx.x * 16;
    int nval = min(16, EC - ebase);

    if (t < 16) {
        sh_ir[t] = (t < nval) ? irec[ebase + t] : 0;
        sh_il[t] = (t < nval) ? ilig[ebase + t] : 0;
    }
    __syncthreads();
    for (int idx = t; idx < nval * 576; idx += 256) {
        int e = idx / 576, j = idx - e * 576;
        sh_w[e * 577 + j] = Wl[(size_t)ebase * 576 + idx];
    }
    for (int idx = t; idx < 640; idx += 256) {
        int e = idx / 40, f = idx - e * 40;
        sh_fl[idx] = g_nodeA[sh_il[e] * 40 + f];
        sh_fr[idx] = g_nodeA[sh_ir[e] * 40 + f];
    }
    if (t < 48) {
        int e = t / 3;
        int ge = (e < nval) ? (ebase + e) : 0;
        sh_r[t] = g_rh[ge * 3 + (t - e * 3)];
    }
    __syncthreads();
    if (t < 128) {
        int e = t >> 3, u = t & 7;
        sh_dot[t] = sh_fl[e * 40 + 16 + u * 3] * sh_r[e * 3]
                  + sh_fl[e * 40 + 17 + u * 3] * sh_r[e * 3 + 1]
                  + sh_fl[e * 40 + 18 + u * 3] * sh_r[e * 3 + 2];
    }
    __syncthreads();
    for (int idx = t; idx < 640; idx += 256) {
        int e = idx / 40, o = idx - e * 40;
        const float* w = sh_w + e * 577;
        const float* f = sh_fl + e * 40;
        float val;
        if (o < 16) {
            float s1 = 0.f, s2 = 0.f;
            #pragma unroll
            for (int u = 0; u < 16; u++) s1 += f[u] * w[u * 16 + o];
            #pragma unroll
            for (int u = 0; u < 8; u++)  s2 += sh_dot[e * 8 + u] * w[256 + u * 16 + o];
            val = PW0_8 * (s1 + s2);
        } else {
            int v = o - 16; int wv = v / 3; int i = v - wv * 3;
            float s1 = 0.f, s2 = 0.f;
            #pragma unroll
            for (int u = 0; u < 16; u++) s1 += f[u] * w[384 + u * 8 + wv];
            #pragma unroll
            for (int u = 0; u < 8; u++)  s2 += f[16 + u * 3 + i] * w[512 + u * 8 + wv];
            val = PW1_8 * s1 * sh_r[e * 3 + i] + PW0_8 * s2;
        }
        sh_le[idx] = val;
    }
    __syncthreads();
    for (int idx = t; idx < 16 * 320; idx += 256) {
        int p = idx >> 4, e = idx & 15;
        if (e >= nval) continue;
        float z;
        if (p < 256) {
            z = sh_le[e * 40 + (p >> 4)] * sh_fr[e * 40 + (p & 15)];
        } else {
            int q = p - 256; int u = q >> 3, v = q & 7;
            z = (sh_le[e * 40 + 16 + u * 3] * sh_fr[e * 40 + 16 + v * 3]
               + sh_le[e * 40 + 17 + u * 3] * sh_fr[e * 40 + 17 + v * 3]
               + sh_le[e * 40 + 18 + u * 3] * sh_fr[e * 40 + 18 + v * 3]) * INV_SQ3;
        }
        g_Zt[(size_t)p * CH + ebase + e] = z;
    }
}

// ---------------------------------------------------------------------------
// Output (chunk-local): out[e,w] = PWREC_8 * sum_k Hr[e,k] * M[e,k*8+w]
// ---------------------------------------------------------------------------
__global__ void k_out(float* __restrict__ outp, int EC) {
    int idx = blockIdx.x * 256 + threadIdx.x;
    int e = idx >> 3, w = idx & 7;
    if (e >= EC) return;
    float s = 0.f;
    #pragma unroll
    for (int k = 0; k < 64; k++)
        s += g_Hr[e * 64 + k] * g_M[(size_t)e * 512 + k * 8 + w];
    outp[idx] = PWREC_8 * s;
}

// ---------------------------------------------------------------------------
extern "C" void kernel_launch(void* const* d_in, const int* in_sizes, int n_in,
                              void* d_out, int out_size) {
    const float* x     = (const float*)d_in[0];
    const float* pos   = (const float*)d_in[1];
    const int*   eidx  = (const int*)  d_in[2];
    const float* eattr = (const float*)d_in[3];
    const int*   iidx  = (const int*)  d_in[4];
    const float* emb_w0= (const float*)d_in[5];
    const float* emb_w1= (const float*)d_in[6];
    const float* imp0  = (const float*)d_in[7];
    const float* m0w0  = (const float*)d_in[8];
    const float* m0w1  = (const float*)d_in[9];
    const float* u0w0  = (const float*)d_in[10];
    const float* u0w1  = (const float*)d_in[11];
    const float* imp1  = (const float*)d_in[12];
    const float* m1w0  = (const float*)d_in[13];
    const float* m1w1  = (const float*)d_in[14];
    const float* u1w0  = (const float*)d_in[15];
    const float* u1w1  = (const float*)d_in[16];
    const float* lw0   = (const float*)d_in[17];
    const float* lw1   = (const float*)d_in[18];
    const float* rw0   = (const float*)d_in[19];
    const float* rw1   = (const float*)d_in[20];
    float* outp = (float*)d_out;

    int N  = in_sizes[0] / 10;
    int E  = in_sizes[2] / 2;
    int EI = in_sizes[4] / 2;
    float degInv = (float)(1.0 / sqrt((double)E / (double)N));

    float *pW, *pZt, *pM, *pHl, *pTW;
    cudaGetSymbolAddress((void**)&pW,  g_Wg);
    cudaGetSymbolAddress((void**)&pZt, g_Zt);
    cudaGetSymbolAddress((void**)&pM,  g_M);
    cudaGetSymbolAddress((void**)&pHl, g_Hl);
    cudaGetSymbolAddress((void**)&pTW, g_tw);

    const int SM_MSGG = (8192 + 4096 + 640 + 320) * 4;
    const int SM_G64  = (64 * 132 + 4096) * 4;
    const int SM_REC  = (8192 + 4096) * 4;
    const int SM_TP   = (18464 + 1280 + 256 + 96) * 4 + 64 * 4;
    const int SM_LIG  = (9232 + 640 + 640 + 128 + 48 + 640) * 4 + 32 * 4;
    cudaFuncSetAttribute(k_wgemm_msg,  cudaFuncAttributeMaxDynamicSharedMemorySize, SM_MSGG);
    cudaFuncSetAttribute(k_gemm64,     cudaFuncAttributeMaxDynamicSharedMemorySize, SM_G64);
    cudaFuncSetAttribute(k_gemm_rec,   cudaFuncAttributeMaxDynamicSharedMemorySize, SM_REC);
    cudaFuncSetAttribute(k_tp_scatter, cudaFuncAttributeMaxDynamicSharedMemorySize, SM_TP);
    cudaFuncSetAttribute(k_lig_tp_z,   cudaFuncAttributeMaxDynamicSharedMemorySize, SM_LIG);

    k_transpose<<<(320 * 512 + 255) / 256, 256>>>(rw1);
    k_embed<<<(N + 7) / 8, 256>>>(x, emb_w0, emb_w1, N);

    // ---- message passes, chunked for L2 residency of W
    for (int pass = 0; pass < 2; pass++) {
        const float* mw0 = pass ? m1w0 : m0w0;
        const float* mw1 = pass ? m1w1 : m0w1;
        for (int e0 = 0; e0 < E; e0 += CH) {
            int ec = min(CH, E - e0);
            dim3 gW(9, (ec + 127) / 128);
            k_wgemm_msg<<<gW, 256, SM_MSGG>>>(eattr + (size_t)e0 * 5, mw0, mw1, pW, ec);
            k_tp_scatter<<<(ec + 31) / 32, 256, SM_TP>>>(
                pos, eidx + e0, eidx + E + e0, pW, ec, pass);
        }
        if (pass == 0)
            k_upd<<<(N + 7) / 8, 256>>>(u0w0, u0w1, imp0, N, degInv, 0);
        else
            k_upd<<<(N + 7) / 8, 256>>>(u1w0, u1w1, imp1, N, degInv, 1);
    }

    // ---- final interaction, chunked
    for (int i0 = 0; i0 < EI; i0 += CH) {
        int ec = min(CH, EI - i0);
        k_prep<<<(ec * 64 + 255) / 256, 256>>>(pos, iidx + i0, iidx + EI + i0,
                                               lw0, rw0, ec);
        dim3 gWl(9, (ec + 127) / 128);
        k_gemm64<<<gWl, 256, SM_G64>>>(pHl, lw1, pW, ec);
        k_lig_tp_z<<<(ec + 15) / 16, 256, SM_LIG>>>(iidx + i0, iidx + EI + i0, pW, ec);
        dim3 gM(8, (ec + 127) / 128);
        k_gemm_rec<<<gM, 256, SM_REC>>>(pZt, pTW, pM, ec);
        k_out<<<(ec * 8 + 255) / 256, 256>>>(outp + (size_t)i0 * 8, ec);
    }
}